// round 3
// baseline (speedup 1.0000x reference)
#include <cuda_runtime.h>
#include <math.h>

// MoE gate: logits = hidden @ gate^T ; softmax over 8 experts; top-2; renormalize.
// hidden: [T, 4096] f32 (T = 16384), gate: [8, 4096] f32.
// Output (flattened f32): [T*2] topk weights, then [T*2] expert indices (as float).

#define NEXP 8
#define HDIM 4096
#define HV   (HDIM / 4)   // float4 per row = 1024
#define TPW  4            // tokens per warp

__global__ __launch_bounds__(256) void moe_gate_kernel(
    const float4* __restrict__ hid,
    const float4* __restrict__ gate,
    float* __restrict__ out,
    int n_tokens)
{
    const int warp = (blockIdx.x * blockDim.x + threadIdx.x) >> 5;
    const int lane = threadIdx.x & 31;
    const int tok0 = warp * TPW;
    if (tok0 >= n_tokens) return;

    float acc[TPW][NEXP];
    #pragma unroll
    for (int t = 0; t < TPW; t++)
        #pragma unroll
        for (int e = 0; e < NEXP; e++)
            acc[t][e] = 0.0f;

    // lanes cover 32 consecutive float4 (=128 floats = 512B) per iter -> coalesced
    #pragma unroll 1
    for (int it = 0; it < HDIM / 128; it++) {
        const int hv = it * 32 + lane;

        float4 g[NEXP];
        #pragma unroll
        for (int e = 0; e < NEXP; e++)
            g[e] = gate[e * HV + hv];          // 128KB total -> L1-resident

        float4 x[TPW];
        #pragma unroll
        for (int t = 0; t < TPW; t++)
            x[t] = hid[(size_t)(tok0 + t) * HV + hv];

        #pragma unroll
        for (int t = 0; t < TPW; t++) {
            #pragma unroll
            for (int e = 0; e < NEXP; e++) {
                acc[t][e] += x[t].x * g[e].x;
                acc[t][e] += x[t].y * g[e].y;
                acc[t][e] += x[t].z * g[e].z;
                acc[t][e] += x[t].w * g[e].w;
            }
        }
    }

    // butterfly reduce: every lane ends with the full dot products
    #pragma unroll
    for (int t = 0; t < TPW; t++) {
        #pragma unroll
        for (int e = 0; e < NEXP; e++) {
            float v = acc[t][e];
            v += __shfl_xor_sync(0xffffffffu, v, 16);
            v += __shfl_xor_sync(0xffffffffu, v, 8);
            v += __shfl_xor_sync(0xffffffffu, v, 4);
            v += __shfl_xor_sync(0xffffffffu, v, 2);
            v += __shfl_xor_sync(0xffffffffu, v, 1);
            acc[t][e] = v;
        }
    }

    float* out_idx = out + (size_t)n_tokens * 2;

    #pragma unroll
    for (int t = 0; t < TPW; t++) {
        if (lane == t) {   // static index into acc[t][*] keeps everything in regs
            const int token = tok0 + t;

            // top-1 (strict > keeps lowest index on ties, matching lax.top_k)
            float b0 = acc[t][0]; int i0 = 0;
            #pragma unroll
            for (int e = 1; e < NEXP; e++)
                if (acc[t][e] > b0) { b0 = acc[t][e]; i0 = e; }

            // top-2
            float b1 = -3.402823466e38f; int i1 = 0;
            #pragma unroll
            for (int e = 0; e < NEXP; e++)
                if (e != i0 && acc[t][e] > b1) { b1 = acc[t][e]; i1 = e; }

            // renormalized top-2 softmax: w0 = e^{l0} / (e^{l0} + e^{l1})
            const float w0 = 1.0f / (1.0f + expf(b1 - b0));
            const float w1 = 1.0f - w0;

            out[token * 2 + 0] = w0;
            out[token * 2 + 1] = w1;
            out_idx[token * 2 + 0] = (float)i0;
            out_idx[token * 2 + 1] = (float)i1;
        }
    }
}

extern "C" void kernel_launch(void* const* d_in, const int* in_sizes, int n_in,
                              void* d_out, int out_size)
{
    const float* hid  = (const float*)d_in[0];   // hidden_states
    const float* gate = (const float*)d_in[1];   // gate_weight
    float* out = (float*)d_out;

    const int n_tokens = in_sizes[0] / HDIM;     // 16384
    const int n_warps  = (n_tokens + TPW - 1) / TPW;
    const int threads  = 256;
    const int blocks   = (n_warps * 32 + threads - 1) / threads;

    moe_gate_kernel<<<blocks, threads>>>(
        (const float4*)hid, (const float4*)gate, out, n_tokens);
}